// round 4
// baseline (speedup 1.0000x reference)
#include <cuda_runtime.h>

// ---------------- problem constants ----------------
#define B_   2
#define L_   2048
#define D_   512
#define P_   32
#define M_   1024
#define H_   8
#define HD_  64
#define WIN_ 256
#define S_   (P_ + L_)     // 2080
#define R_   (B_ * S_)     // 4160
#define EPS_ 1e-5f

// packed fp32x2 FMA (SASS FFMA2) and unpack
#define FMA2(acc, a, b) \
    asm("fma.rn.f32x2 %0, %1, %2, %0;" : "+l"(acc) : "l"(a), "l"(b))
#define UNPK(lo, hi, u) \
    asm("mov.b64 {%0, %1}, %2;" : "=f"(lo), "=f"(hi) : "l"(u))

// ---------------- scratch (device globals, no allocation) ----------------
__device__ float g_combined[R_ * D_];
__device__ float g_k[R_ * D_];
__device__ float g_v[R_ * D_];
__device__ float g_q[R_ * D_];
__device__ float g_w[R_ * M_];          // w_write
__device__ float g_w2[R_ * M_];         // w_read
__device__ float g_state[B_ * M_ * D_];
__device__ float g_memout[R_ * D_];
__device__ float g_h[R_ * D_];
__device__ float g_qh[R_ * D_];
__device__ float g_kh[R_ * D_];
__device__ float g_vh[R_ * D_];
__device__ float g_aout[R_ * D_];
__device__ float g_ao2[R_ * D_];
__device__ float g_h2[R_ * D_];

// ---------------- concat: combined = [persistent ; x] ----------------
__global__ void concat_kernel(const float* __restrict__ x,
                              const float* __restrict__ pm,
                              float* __restrict__ c) {
    long i = (long)blockIdx.x * 256 + threadIdx.x;
    if (i >= (long)R_ * D_) return;
    int d = (int)(i % D_);
    long sd = i / D_;
    int s = (int)(sd % S_);
    int b = (int)(sd / S_);
    c[i] = (s < P_) ? pm[s * D_ + d]
                    : x[((long)b * L_ + (s - P_)) * D_ + d];
}

// ---------------- fp32 GEMM core: 128x128x16 tile, 256 threads, FFMA2 ----
// C[M x N] = A @ B (+ optional bias over N).
// AMODE=0: A row-major M x K.  AMODE=1: A stored K x M (use A^T, ld M).
// BMODE=0: B row-major K x N.  BMODE=1: B stored N x K (use B^T, ld K).
// Requirements: K % 16 == 0, N % 128 == 0; M guarded.
// Thread (tm=tid>>4, tn=tid&15) computes rows tm*8..+7, cols tn*8..+7.
// A is stored DUPLICATED in smem (As[k][2m]=As[k][2m+1]=A[m][k]) so the
// broadcast operand arrives pre-packed {a,a} for fma.rn.f32x2.
template<int AMODE, int BMODE>
__device__ __forceinline__ void gemm_core_f2(
    const float* __restrict__ A, const float* __restrict__ Bm,
    float* __restrict__ C, int M, int N, int K, const float* __restrict__ bias) {
    __shared__ __align__(16) float As[2][16][256];   // 32 KB
    __shared__ __align__(16) float Bs[2][16][128];   // 16 KB
    const int tid = threadIdx.x;
    const int tn = tid & 15, tm = tid >> 4;
    const int m0 = blockIdx.y * 128, n0 = blockIdx.x * 128;

    unsigned long long acc[8][4];
#pragma unroll
    for (int i = 0; i < 8; i++)
#pragma unroll
        for (int j = 0; j < 4; j++) acc[i][j] = 0ull;

    float4 pa0, pa1, pb0, pb1;

    auto loadA = [&](int k0) {
        if (AMODE == 0) {
            int row = tid >> 2, kq = (tid & 3) << 2;
            pa0 = (m0 + row < M)
                ? *(const float4*)(A + (long)(m0 + row) * K + k0 + kq)
                : make_float4(0.f, 0.f, 0.f, 0.f);
            pa1 = (m0 + 64 + row < M)
                ? *(const float4*)(A + (long)(m0 + 64 + row) * K + k0 + kq)
                : make_float4(0.f, 0.f, 0.f, 0.f);
        } else {
            int k = tid >> 5, mq = (tid & 31) << 2;
            bool ok = (m0 + mq < M);
            pa0 = ok ? *(const float4*)(A + (long)(k0 + k) * M + m0 + mq)
                     : make_float4(0.f, 0.f, 0.f, 0.f);
            pa1 = ok ? *(const float4*)(A + (long)(k0 + k + 8) * M + m0 + mq)
                     : make_float4(0.f, 0.f, 0.f, 0.f);
        }
    };
    auto storeA = [&](int b) {
        if (AMODE == 0) {
            int row = tid >> 2, kq = (tid & 3) << 2;
#pragma unroll
            for (int i = 0; i < 4; i++) {
                float va = (&pa0.x)[i], vb = (&pa1.x)[i];
                *(float2*)&As[b][kq + i][2 * row]        = make_float2(va, va);
                *(float2*)&As[b][kq + i][2 * (row + 64)] = make_float2(vb, vb);
            }
        } else {
            int k = tid >> 5, mq = (tid & 31) << 2;
#pragma unroll
            for (int i = 0; i < 4; i++) {
                float va = (&pa0.x)[i], vb = (&pa1.x)[i];
                *(float2*)&As[b][k][2 * (mq + i)]     = make_float2(va, va);
                *(float2*)&As[b][k + 8][2 * (mq + i)] = make_float2(vb, vb);
            }
        }
    };
    auto loadB = [&](int k0) {
        if (BMODE == 0) {
            int k = tid >> 5, nq = (tid & 31) << 2;
            pb0 = *(const float4*)(Bm + (long)(k0 + k) * N + n0 + nq);
            pb1 = *(const float4*)(Bm + (long)(k0 + k + 8) * N + n0 + nq);
        } else {
            int col = tid >> 2, kq = (tid & 3) << 2;
            pb0 = *(const float4*)(Bm + (long)(n0 + col) * K + k0 + kq);
            pb1 = *(const float4*)(Bm + (long)(n0 + 64 + col) * K + k0 + kq);
        }
    };
    auto storeB = [&](int b) {
        if (BMODE == 0) {
            int k = tid >> 5, nq = (tid & 31) << 2;
            *(float4*)&Bs[b][k][nq]     = pb0;
            *(float4*)&Bs[b][k + 8][nq] = pb1;
        } else {
            int col = tid >> 2, kq = (tid & 3) << 2;
#pragma unroll
            for (int i = 0; i < 4; i++) {
                Bs[b][kq + i][col]      = (&pb0.x)[i];
                Bs[b][kq + i][64 + col] = (&pb1.x)[i];
            }
        }
    };

    const int slabs = K / 16;
    loadA(0); loadB(0);
    storeA(0); storeB(0);
    __syncthreads();
    int buf = 0;

    for (int s = 0; s < slabs; s++) {
        if (s + 1 < slabs) {
            loadA((s + 1) * 16); loadB((s + 1) * 16);
            storeA(buf ^ 1);     storeB(buf ^ 1);
        }
#pragma unroll
        for (int k = 0; k < 16; k++) {
            unsigned long long a2[8], b2[4];
#pragma unroll
            for (int j = 0; j < 4; j++) {
                ulonglong2 u = *reinterpret_cast<const ulonglong2*>(
                    &As[buf][k][tm * 16 + 4 * j]);
                a2[2 * j] = u.x; a2[2 * j + 1] = u.y;
            }
            {
                ulonglong2 u0 = *reinterpret_cast<const ulonglong2*>(
                    &Bs[buf][k][tn * 8]);
                ulonglong2 u1 = *reinterpret_cast<const ulonglong2*>(
                    &Bs[buf][k][tn * 8 + 4]);
                b2[0] = u0.x; b2[1] = u0.y; b2[2] = u1.x; b2[3] = u1.y;
            }
#pragma unroll
            for (int i = 0; i < 8; i++)
#pragma unroll
                for (int j = 0; j < 4; j++)
                    FMA2(acc[i][j], a2[i], b2[j]);
        }
        __syncthreads();
        buf ^= 1;
    }

    // --- epilogue ---
    float bv[8];
#pragma unroll
    for (int j = 0; j < 8; j++) bv[j] = 0.f;
    if (bias) {
        float4 t0 = *(const float4*)(bias + n0 + tn * 8);
        float4 t1 = *(const float4*)(bias + n0 + tn * 8 + 4);
        bv[0] = t0.x; bv[1] = t0.y; bv[2] = t0.z; bv[3] = t0.w;
        bv[4] = t1.x; bv[5] = t1.y; bv[6] = t1.z; bv[7] = t1.w;
    }
#pragma unroll
    for (int i = 0; i < 8; i++) {
        int m = m0 + tm * 8 + i;
        if (m < M) {
            float o[8];
#pragma unroll
            for (int j = 0; j < 4; j++) UNPK(o[2 * j], o[2 * j + 1], acc[i][j]);
#pragma unroll
            for (int j = 0; j < 8; j++) o[j] += bv[j];
            float* crow = C + (long)m * N + n0 + tn * 8;
            *(float4*)(crow)     = make_float4(o[0], o[1], o[2], o[3]);
            *(float4*)(crow + 4) = make_float4(o[4], o[5], o[6], o[7]);
        }
    }
}

template<int AMODE, int BMODE>
__global__ void __launch_bounds__(256, 2)
gemm_kernel(const float* __restrict__ A, const float* __restrict__ Bm,
            float* __restrict__ C, int M, int N, int K,
            long sA, long sB, long sC, const float* __restrict__ bias) {
    A  += (long)blockIdx.z * sA;
    Bm += (long)blockIdx.z * sB;
    C  += (long)blockIdx.z * sC;
    gemm_core_f2<AMODE, BMODE>(A, Bm, C, M, N, K, bias);
}

// 3 GEMMs sharing the same A, distinct B/C, selected by blockIdx.z.
struct Ptr3 { const float* b0; const float* b1; const float* b2;
              float* c0; float* c1; float* c2; };
__global__ void __launch_bounds__(256, 2)
gemm3_kernel(const float* __restrict__ A, Ptr3 p, int M, int N, int K) {
    const float* Bm = (blockIdx.z == 0) ? p.b0 : (blockIdx.z == 1) ? p.b1 : p.b2;
    float*       C  = (blockIdx.z == 0) ? p.c0 : (blockIdx.z == 1) ? p.c1 : p.c2;
    gemm_core_f2<0, 0>(A, Bm, C, M, N, K, nullptr);
}

// 2 GEMMs sharing the same B (mem_keys, used transposed), distinct A/C.
struct PtrW { const float* a0; const float* a1; float* c0; float* c1; };
__global__ void __launch_bounds__(256, 2)
gemmW_kernel(PtrW p, const float* __restrict__ mk, int M, int N, int K) {
    const float* A = blockIdx.z ? p.a1 : p.a0;
    float*       C = blockIdx.z ? p.c1 : p.c0;
    gemm_core_f2<0, 1>(A, mk, C, M, N, K, nullptr);
}

// ---------------- row softmax over 1024 cols ----------------
__global__ void __launch_bounds__(256) softmax1024(float* __restrict__ w) {
    __shared__ float sh[8];
    float* row = w + (long)blockIdx.x * M_;
    const int tid = threadIdx.x;
    float4 v = *(float4*)(row + tid * 4);
    float mx = fmaxf(fmaxf(v.x, v.y), fmaxf(v.z, v.w));
#pragma unroll
    for (int o = 16; o; o >>= 1) mx = fmaxf(mx, __shfl_xor_sync(~0u, mx, o));
    if ((tid & 31) == 0) sh[tid >> 5] = mx;
    __syncthreads();
    mx = sh[0];
#pragma unroll
    for (int i = 1; i < 8; i++) mx = fmaxf(mx, sh[i]);
    v.x = __expf(v.x - mx); v.y = __expf(v.y - mx);
    v.z = __expf(v.z - mx); v.w = __expf(v.w - mx);
    float s = v.x + v.y + v.z + v.w;
#pragma unroll
    for (int o = 16; o; o >>= 1) s += __shfl_xor_sync(~0u, s, o);
    __syncthreads();
    if ((tid & 31) == 0) sh[tid >> 5] = s;
    __syncthreads();
    s = sh[0] + sh[1] + sh[2] + sh[3] + sh[4] + sh[5] + sh[6] + sh[7];
    float inv = 1.f / s;
    v.x *= inv; v.y *= inv; v.z *= inv; v.w *= inv;
    *(float4*)(row + tid * 4) = v;
}

// ---------------- layernorm, row width 512, 128 threads ----------------
__global__ void __launch_bounds__(128)
layernorm512(const float* __restrict__ in, float* __restrict__ out,
             const float* __restrict__ gw, const float* __restrict__ bw) {
    __shared__ float sh[4];
    const int tid = threadIdx.x;
    const float* row = in + (long)blockIdx.x * D_;
    float4 v = *(const float4*)(row + tid * 4);
    float s = v.x + v.y + v.z + v.w;
#pragma unroll
    for (int o = 16; o; o >>= 1) s += __shfl_xor_sync(~0u, s, o);
    if ((tid & 31) == 0) sh[tid >> 5] = s;
    __syncthreads();
    float mu = (sh[0] + sh[1] + sh[2] + sh[3]) * (1.f / 512.f);
    float dx = v.x - mu, dy = v.y - mu, dz = v.z - mu, dw = v.w - mu;
    float sq = dx * dx + dy * dy + dz * dz + dw * dw;
#pragma unroll
    for (int o = 16; o; o >>= 1) sq += __shfl_xor_sync(~0u, sq, o);
    __syncthreads();
    if ((tid & 31) == 0) sh[tid >> 5] = sq;
    __syncthreads();
    float var = (sh[0] + sh[1] + sh[2] + sh[3]) * (1.f / 512.f);
    float inv = rsqrtf(var + EPS_);
    float4 g4 = *(const float4*)(gw + tid * 4);
    float4 b4 = *(const float4*)(bw + tid * 4);
    float4 o;
    o.x = dx * inv * g4.x + b4.x;
    o.y = dy * inv * g4.y + b4.y;
    o.z = dz * inv * g4.z + b4.z;
    o.w = dw * inv * g4.w + b4.w;
    *(float4*)(out + (long)blockIdx.x * D_ + tid * 4) = o;
}

// ---------------- banded flash attention ----------------
#define ATTN_SMEM_FLOATS (64 * 65 * 2 + 64 * 64 * 2)
__global__ void __launch_bounds__(256)
attn_kernel(const float* __restrict__ qh, const float* __restrict__ kh,
            const float* __restrict__ vh, float* __restrict__ out) {
    extern __shared__ float smem[];
    float (*Qs)[65] = (float (*)[65])smem;                 // 64x65
    float (*Ps)[65] = (float (*)[65])(smem + 64 * 65);     // 64x65
    float (*Ks)[64] = (float (*)[64])(smem + 64 * 65 * 2); // 64x64
    float (*Vs)[64] = (float (*)[64])(smem + 64 * 65 * 2 + 64 * 64);

    const int qt = blockIdx.x, h = blockIdx.y, b = blockIdx.z;
    const int q0 = qt * 64;
    const int tid = threadIdx.x;
    const int r = tid >> 2, cg = tid & 3;
    const long base = (long)b * S_ * D_ + h * HD_;

    for (int i = tid; i < 64 * 64; i += 256) {
        int rr = i >> 6, dd = i & 63;
        Qs[rr][dd] = (q0 + rr < S_) ? qh[base + (long)(q0 + rr) * D_ + dd] : 0.f;
    }

    float m = -1e30f, l = 0.f;
    float o[16];
#pragma unroll
    for (int i = 0; i < 16; i++) o[i] = 0.f;

    int klo = q0 - (WIN_ - 1); if (klo < 0) klo = 0;
    int khi = q0 + 63 + WIN_ - 1; if (khi > S_ - 1) khi = S_ - 1;

    for (int kt = klo >> 6; kt <= khi >> 6; ++kt) {
        const int k0 = kt << 6;
        __syncthreads();
        for (int i = tid; i < 64 * 64; i += 256) {
            int rr = i >> 6, dd = i & 63;
            bool ok = (k0 + rr < S_);
            long g = base + (long)(k0 + rr) * D_ + dd;
            Ks[rr][dd] = ok ? kh[g] : 0.f;
            Vs[rr][dd] = ok ? vh[g] : 0.f;
        }
        __syncthreads();

        float sreg[16];
#pragma unroll
        for (int j = 0; j < 16; j++) sreg[j] = 0.f;
#pragma unroll 8
        for (int d = 0; d < 64; d++) {
            float qd = Qs[r][d];
#pragma unroll
            for (int j = 0; j < 16; j++) sreg[j] += qd * Ks[cg * 16 + j][d];
        }

        const int qi = q0 + r;
        float tmax = -1e30f;
#pragma unroll
        for (int j = 0; j < 16; j++) {
            int kj = k0 + cg * 16 + j;
            int diff = qi - kj; if (diff < 0) diff = -diff;
            bool valid = (kj < S_) && (diff < WIN_);
            sreg[j] = valid ? sreg[j] * 0.125f : -1e30f;
            tmax = fmaxf(tmax, sreg[j]);
        }
        tmax = fmaxf(tmax, __shfl_xor_sync(0xffffffffu, tmax, 1));
        tmax = fmaxf(tmax, __shfl_xor_sync(0xffffffffu, tmax, 2));
        float mnew = fmaxf(m, tmax);
        float alpha = __expf(m - mnew);
        float lsum = 0.f;
#pragma unroll
        for (int j = 0; j < 16; j++) {
            // masked (sentinel) entries must contribute exactly 0, even when
            // mnew is itself the sentinel (fully-masked tile for this row).
            float p = (sreg[j] > -0.9e30f) ? __expf(sreg[j] - mnew) : 0.f;
            Ps[r][cg * 16 + j] = p;
            lsum += p;
        }
        lsum += __shfl_xor_sync(0xffffffffu, lsum, 1);
        lsum += __shfl_xor_sync(0xffffffffu, lsum, 2);
        l = l * alpha + lsum;
        m = mnew;
#pragma unroll
        for (int i = 0; i < 16; i++) o[i] *= alpha;
        __syncthreads();
#pragma unroll 4
        for (int j = 0; j < 64; j++) {
            float p = Ps[r][j];
#pragma unroll
            for (int i = 0; i < 16; i++) o[i] += p * Vs[j][cg * 16 + i];
        }
    }

    const int qi = q0 + r;
    if (qi < S_) {
        float inv = 1.f / l;
        float* orow = out + base + (long)qi * D_ + cg * 16;
#pragma unroll
        for (int i = 0; i < 16; i++) orow[i] = o[i] * inv;
    }
}

// ---------------- launch ----------------
extern "C" void kernel_launch(void* const* d_in, const int* in_sizes, int n_in,
                              void* d_out, int out_size) {
    const float* x        = (const float*)d_in[0];
    const float* pm       = (const float*)d_in[1];
    const float* mem_keys = (const float*)d_in[2];
    const float* mem_Wk   = (const float*)d_in[3];
    const float* mem_Wv   = (const float*)d_in[4];
    const float* mem_Wq   = (const float*)d_in[5];
    const float* attn_Wq  = (const float*)d_in[6];
    const float* attn_Wk  = (const float*)d_in[7];
    const float* attn_Wv  = (const float*)d_in[8];
    const float* attn_Wo  = (const float*)d_in[9];
    const float* ln1_g    = (const float*)d_in[10];
    const float* ln1_b    = (const float*)d_in[11];
    const float* ln2_g    = (const float*)d_in[12];
    const float* ln2_b    = (const float*)d_in[13];
    const float* out_W    = (const float*)d_in[14];
    const float* out_b    = (const float*)d_in[15];
    float* out = (float*)d_out;

    float *combined, *k, *v, *q, *w, *w2, *state, *memout, *h;
    float *qh, *kh, *vh, *aout, *ao2, *h2;
    cudaGetSymbolAddress((void**)&combined, g_combined);
    cudaGetSymbolAddress((void**)&k, g_k);
    cudaGetSymbolAddress((void**)&v, g_v);
    cudaGetSymbolAddress((void**)&q, g_q);
    cudaGetSymbolAddress((void**)&w, g_w);
    cudaGetSymbolAddress((void**)&w2, g_w2);
    cudaGetSymbolAddress((void**)&state, g_state);
    cudaGetSymbolAddress((void**)&memout, g_memout);
    cudaGetSymbolAddress((void**)&h, g_h);
    cudaGetSymbolAddress((void**)&qh, g_qh);
    cudaGetSymbolAddress((void**)&kh, g_kh);
    cudaGetSymbolAddress((void**)&vh, g_vh);
    cudaGetSymbolAddress((void**)&aout, g_aout);
    cudaGetSymbolAddress((void**)&ao2, g_ao2);
    cudaGetSymbolAddress((void**)&h2, g_h2);

    cudaFuncSetAttribute(attn_kernel,
                         cudaFuncAttributeMaxDynamicSharedMemorySize,
                         ATTN_SMEM_FLOATS * (int)sizeof(float));

    // 1. combined = [pm ; x]
    concat_kernel<<<(int)(((long)R_ * D_ + 255) / 256), 256>>>(x, pm, combined);

    const int MT = (R_ + 127) / 128;                // 33 row tiles

    // 2. memory k/v/q projections (batched, 396 CTAs)
    {
        Ptr3 p{mem_Wk, mem_Wv, mem_Wq, k, v, q};
        dim3 g(512 / 128, MT, 3);
        gemm3_kernel<<<g, 256>>>(combined, p, R_, D_, D_);
    }

    // 3. both gating GEMMs together: w_write = k@mkT, w_read = q@mkT (528 CTAs)
    {
        PtrW p{k, q, w, w2};
        dim3 g(1024 / 128, MT, 2);
        gemmW_kernel<<<g, 256>>>(p, mem_keys, R_, M_, D_);
    }
    softmax1024<<<R_, 256>>>(w);
    softmax1024<<<R_, 256>>>(w2);

    // 4. state[b] = w_write[b]^T @ v[b]   (M=1024, N=512, K=S)
    {
        dim3 gs(512 / 128, 1024 / 128, B_);
        gemm_kernel<1, 0><<<gs, 256>>>(w, v, state, M_, D_, S_,
                                       (long)S_ * M_, (long)S_ * D_, (long)M_ * D_, nullptr);
    }

    // 5. mem_out[b] = w_read[b] @ state[b]   (M=S, N=512, K=1024)
    {
        dim3 gm(512 / 128, (S_ + 127) / 128, B_);
        gemm_kernel<0, 0><<<gm, 256>>>(w2, state, memout, S_, D_, M_,
                                       (long)S_ * M_, (long)M_ * D_, (long)S_ * D_, nullptr);
    }

    // 6. LN1
    layernorm512<<<R_, 128>>>(memout, h, ln1_g, ln1_b);

    // 7. attention projections (batched)
    {
        Ptr3 p{attn_Wq, attn_Wk, attn_Wv, qh, kh, vh};
        dim3 g(512 / 128, MT, 3);
        gemm3_kernel<<<g, 256>>>(h, p, R_, D_, D_);
    }

    // 8. banded flash attention
    {
        dim3 ga((S_ + 63) / 64, H_, B_);
        attn_kernel<<<ga, 256, ATTN_SMEM_FLOATS * (int)sizeof(float)>>>(qh, kh, vh, aout);
    }

    // 9. output projection + LN2 + final linear (+bias)
    {
        dim3 g(512 / 128, MT, 1);
        gemm_kernel<0, 0><<<g, 256>>>(aout, attn_Wo, ao2, R_, D_, D_, 0, 0, 0, nullptr);
        layernorm512<<<R_, 128>>>(ao2, h2, ln2_g, ln2_b);
        gemm_kernel<0, 0><<<g, 256>>>(h2, out_W, out, R_, D_, D_, 0, 0, 0, out_b);
    }
}